// round 14
// baseline (speedup 1.0000x reference)
#include <cuda_runtime.h>
#include <cuda_fp16.h>
#include <cstdint>

#define D     512
#define NTR   16384
#define NT    8192
#define NCLS  16

#define SCHUNK   256                 // j per staged chunk
#define NSCU     4                   // chunks per attn unit (1024 j)
#define MTILE    64                  // i rows per attn unit (4 warps x 16)
#define YSTR     24                  // halves per padded ytr row (48B, conflict-free ldmatrix)
#define NSLOT    16                  // partial slots: (split, half)

#define LOG2E  1.4426950408889634f
#define MS2    (-8.656170245333781f)   // -6 nats in log2 units, softmax-invariant shift

// ---- ticket queue layout ----
#define TQ       256                 // q items: 32 rows each
#define TPROJ    (TQ + 512)          // + 64 chunks x (4 k-items + 4 y-items), 64 rows each
#define TATT     2048                // attn units: (x, split, half)
#define NTICK    (TPROJ + TATT)

#define GRID_FUSED 1184

// ---------------- device scratch ----------------
__device__ float2 g_q[NT];
__device__ float2 g_k[NTR];
__device__ uint4  g_y16[NTR * 2];
__device__ float  g_pnum[NSLOT * NT * NCLS];
__device__ float  g_pden[NSLOT * NT];
__device__ int    g_ticket;          // reset by reduce_kernel each launch
__device__ int    g_qcnt;
__device__ int    g_ccnt[64];

// ---------------- helpers ----------------
__device__ __forceinline__ float ex2f(float x) {
    float r; asm("ex2.approx.ftz.f32 %0, %1;" : "=f"(r) : "f"(x)); return r;
}
__device__ __forceinline__ uint32_t cvt_f16x2(float hi, float lo) {
    uint32_t r; asm("cvt.rn.f16x2.f32 %0, %1, %2;" : "=r"(r) : "f"(hi), "f"(lo)); return r;
}
__device__ __forceinline__ uint32_t smem_u32(const void* p) {
    uint32_t a;
    asm("{ .reg .u64 t; cvta.to.shared.u64 t, %1; cvt.u32.u64 %0, t; }" : "=r"(a) : "l"(p));
    return a;
}
__device__ __forceinline__ void ldmatrix_x4_trans(uint32_t& r0, uint32_t& r1,
                                                  uint32_t& r2, uint32_t& r3,
                                                  uint32_t addr) {
    asm volatile("ldmatrix.sync.aligned.m8n8.x4.trans.shared.b16 {%0,%1,%2,%3}, [%4];"
                 : "=r"(r0), "=r"(r1), "=r"(r2), "=r"(r3) : "r"(addr));
}
__device__ __forceinline__ void mma16816(float& c0, float& c1, float& c2, float& c3,
                                         uint32_t a0, uint32_t a1, uint32_t a2, uint32_t a3,
                                         uint32_t b0, uint32_t b1) {
    asm volatile("mma.sync.aligned.m16n8k16.row.col.f32.f16.f16.f32 "
                 "{%0,%1,%2,%3}, {%4,%5,%6,%7}, {%8,%9}, {%0,%1,%2,%3};"
                 : "+f"(c0), "+f"(c1), "+f"(c2), "+f"(c3)
                 : "r"(a0), "r"(a1), "r"(a2), "r"(a3), "r"(b0), "r"(b1));
}
__device__ __forceinline__ void spin_until(volatile int* p, int target) {
    if (*p < target) {
        while (*p < target) __nanosleep(64);
    }
}

// projection of consecutive rows (4 warps, rpw rows per warp) — round-8 math
__device__ __forceinline__ void proj_rows(const float* __restrict__ src, float2* dst,
                                          int base, int rpw, float scale,
                                          const float* sA0t, const float* sA1t,
                                          int warp, int lane) {
    float a0[16], a1[16];
    #pragma unroll
    for (int it = 0; it < 4; it++) {
        #pragma unroll
        for (int u = 0; u < 4; u++) {
            int idx = it * 128 + u * 32 + lane;
            a0[it * 4 + u] = sA0t[idx];
            a1[it * 4 + u] = sA1t[idx];
        }
    }
    int row0 = base + warp * rpw;
    for (int r = 0; r < rpw; r++) {
        const float4* xr4 = reinterpret_cast<const float4*>(src + (size_t)(row0 + r) * D);
        float4 x0 = xr4[lane];
        float4 x1 = xr4[32 + lane];
        float4 x2 = xr4[64 + lane];
        float4 x3 = xr4[96 + lane];

        float s0, s1;
        s0 =      x0.x * a0[0];            s1 =      x0.x * a1[0];
        s0 = fmaf(x0.y, a0[1],  s0);       s1 = fmaf(x0.y, a1[1],  s1);
        s0 = fmaf(x0.z, a0[2],  s0);       s1 = fmaf(x0.z, a1[2],  s1);
        s0 = fmaf(x0.w, a0[3],  s0);       s1 = fmaf(x0.w, a1[3],  s1);
        s0 = fmaf(x1.x, a0[4],  s0);       s1 = fmaf(x1.x, a1[4],  s1);
        s0 = fmaf(x1.y, a0[5],  s0);       s1 = fmaf(x1.y, a1[5],  s1);
        s0 = fmaf(x1.z, a0[6],  s0);       s1 = fmaf(x1.z, a1[6],  s1);
        s0 = fmaf(x1.w, a0[7],  s0);       s1 = fmaf(x1.w, a1[7],  s1);
        s0 = fmaf(x2.x, a0[8],  s0);       s1 = fmaf(x2.x, a1[8],  s1);
        s0 = fmaf(x2.y, a0[9],  s0);       s1 = fmaf(x2.y, a1[9],  s1);
        s0 = fmaf(x2.z, a0[10], s0);       s1 = fmaf(x2.z, a1[10], s1);
        s0 = fmaf(x2.w, a0[11], s0);       s1 = fmaf(x2.w, a1[11], s1);
        s0 = fmaf(x3.x, a0[12], s0);       s1 = fmaf(x3.x, a1[12], s1);
        s0 = fmaf(x3.y, a0[13], s0);       s1 = fmaf(x3.y, a1[13], s1);
        s0 = fmaf(x3.z, a0[14], s0);       s1 = fmaf(x3.z, a1[14], s1);
        s0 = fmaf(x3.w, a0[15], s0);       s1 = fmaf(x3.w, a1[15], s1);

        #pragma unroll
        for (int off = 16; off > 0; off >>= 1) {
            s0 += __shfl_xor_sync(0xFFFFFFFFu, s0, off);
            s1 += __shfl_xor_sync(0xFFFFFFFFu, s1, off);
        }
        if (lane == 0) dst[row0 + r] = make_float2(s0 * scale, s1 * scale);
    }
}

// ---------------- fused persistent producer/consumer kernel ----------------
__global__ __launch_bounds__(128, 6) void fused_kernel(const float* __restrict__ xtr,
                                                       const float* __restrict__ ytr,
                                                       const float* __restrict__ xt,
                                                       const float* __restrict__ A) {
    // 16-aligned big arrays first; scalars last (STS.128 targets must stay 16B-aligned)
    __shared__ __align__(16) float2 sk[2][SCHUNK];         // 4KB
    __shared__ __align__(16) __half sy[2][SCHUNK * YSTR];  // 24KB
    __shared__ __align__(16) float sA0t[D];
    __shared__ __align__(16) float sA1t[D];
    __shared__ int s_t;

    int tid  = threadIdx.x;
    int warp = tid >> 5;
    int lane = tid & 31;

    // stage transposed A once per CTA
    for (int c = tid; c < D; c += 128) {
        float2 a = reinterpret_cast<const float2*>(A)[c];
        int idx = (c >> 7) * 128 + (c & 3) * 32 + ((c >> 2) & 31);
        sA0t[idx] = a.x; sA1t[idx] = a.y;
    }

    for (;;) {
        __syncthreads();                 // protects s_t (write-after-read) + sA on first pass
        if (tid == 0) s_t = atomicAdd(&g_ticket, 1);
        __syncthreads();
        int t = s_t;
        if (t >= NTICK) break;

        if (t < TQ) {
            // ---- q item: 32 rows ----
            proj_rows(xt, g_q, t * 32, 8, LOG2E, sA0t, sA1t, warp, lane);
            __threadfence();
            __syncthreads();
            if (tid == 0) atomicAdd(&g_qcnt, 1);
        } else if (t < TPROJ) {
            // ---- k / y item: 64 rows of chunk ci ----
            int u2 = t - TQ;
            int ci = u2 >> 3;            // global chunk 0..63
            int u  = u2 & 7;
            int rowb = ci * 256;
            if (u < 4) {
                proj_rows(xtr, g_k, rowb + u * 64, 16, 1.0f, sA0t, sA1t, warp, lane);
            } else {
                int row = rowb + (u - 4) * 64 + (tid >> 1);
                const float4* srcy =
                    reinterpret_cast<const float4*>(ytr + (size_t)row * NCLS) + (tid & 1) * 2;
                float4 v0 = srcy[0], v1 = srcy[1];
                uint4 o;
                o.x = cvt_f16x2(v0.y, v0.x); o.y = cvt_f16x2(v0.w, v0.z);
                o.z = cvt_f16x2(v1.y, v1.x); o.w = cvt_f16x2(v1.w, v1.z);
                g_y16[row * 2 + (tid & 1)] = o;
            }
            __threadfence();
            __syncthreads();
            if (tid == 0) atomicAdd(&g_ccnt[ci], 1);
        } else {
            // ---- attn unit: (x, split, half), 64 i-rows x 1024 j ----
            int a    = t - TPROJ;
            int s    = a >> 8;
            int rr   = a & 255;
            int x    = rr >> 1;
            int half = rr & 1;
            int cb   = s * 8 + half * 4;
            int j0   = s * 2048 + half * 1024;

            if (tid == 0) {
                spin_until(&g_qcnt, TQ);
                spin_until(&g_ccnt[cb], 8);
                spin_until(&g_ccnt[cb + 1], 8);
                __threadfence();
            }
            __syncthreads();

            int g  = lane >> 2;
            int tg = lane & 3;
            int r0 = x * MTILE + warp * 16 + g;
            int r1 = r0 + 8;
            float2 qg = g_q[r0];
            float2 qh = g_q[r1];

            float d10 = 0, d11 = 0, d12 = 0, d13 = 0;
            float d20 = 0, d21 = 0, d22 = 0, d23 = 0;
            float e0 = 0, e1 = 0, e2 = 0, e3 = 0;
            const uint32_t ONES = 0x3C003C00u;

            float4 pk;  uint4 py0, py1, py2, py3;

#define LDG_CHUNK(sc) do {                                                   \
            int jb = j0 + (sc) * SCHUNK;                                     \
            pk = reinterpret_cast<const float4*>(g_k)[(jb >> 1) + tid];      \
            int rr2 = (jb + 2 * tid) * 2;                                    \
            py0 = g_y16[rr2]; py1 = g_y16[rr2 + 1];                          \
            py2 = g_y16[rr2 + 2]; py3 = g_y16[rr2 + 3];                      \
        } while (0)

#define STS_CHUNK(b) do {                                                    \
            reinterpret_cast<float4*>(sk[b])[tid] = pk;                      \
            uint4* dr0 = reinterpret_cast<uint4*>(&sy[b][(2 * tid) * YSTR]); \
            dr0[0] = py0; dr0[1] = py1;                                      \
            uint4* dr1 = reinterpret_cast<uint4*>(&sy[b][(2 * tid + 1) * YSTR]); \
            dr1[0] = py2; dr1[1] = py3;                                      \
        } while (0)

            LDG_CHUNK(0);
            STS_CHUNK(0);
            LDG_CHUNK(1);
            __syncthreads();

            for (int sc = 0; sc < NSCU; sc++) {
                int b = sc & 1;
                const float4* k4 = reinterpret_cast<const float4*>(sk[b]);
                uint32_t ybase = smem_u32(&sy[b][(lane & 15) * YSTR]) + (lane >> 4) * 16;

                #pragma unroll 4
                for (int ks = 0; ks < SCHUNK / 16; ks++) {
                    float4 ka = k4[ks * 8 + tg];
                    float4 kb = k4[ks * 8 + 4 + tg];

                    float wg0 = ex2f(fmaf(qg.x, ka.x, fmaf(qg.y, ka.y, MS2)));
                    float wg1 = ex2f(fmaf(qg.x, ka.z, fmaf(qg.y, ka.w, MS2)));
                    float wg2 = ex2f(fmaf(qg.x, kb.x, fmaf(qg.y, kb.y, MS2)));
                    float wg3 = ex2f(fmaf(qg.x, kb.z, fmaf(qg.y, kb.w, MS2)));
                    float wh0 = ex2f(fmaf(qh.x, ka.x, fmaf(qh.y, ka.y, MS2)));
                    float wh1 = ex2f(fmaf(qh.x, ka.z, fmaf(qh.y, ka.w, MS2)));
                    float wh2 = ex2f(fmaf(qh.x, kb.x, fmaf(qh.y, kb.y, MS2)));
                    float wh3 = ex2f(fmaf(qh.x, kb.z, fmaf(qh.y, kb.w, MS2)));

                    uint32_t a0 = cvt_f16x2(wg1, wg0);
                    uint32_t a1 = cvt_f16x2(wh1, wh0);
                    uint32_t a2 = cvt_f16x2(wg3, wg2);
                    uint32_t a3 = cvt_f16x2(wh3, wh2);

                    uint32_t b0, b1, b2, b3;
                    ldmatrix_x4_trans(b0, b1, b2, b3, ybase + (ks * 16) * (YSTR * 2));

                    mma16816(d10, d11, d12, d13, a0, a1, a2, a3, b0, b1);
                    mma16816(d20, d21, d22, d23, a0, a1, a2, a3, b2, b3);
                    mma16816(e0, e1, e2, e3, a0, a1, a2, a3, ONES, ONES);
                }

                if (sc + 1 < NSCU) STS_CHUNK(b ^ 1);
                if (sc + 2 < NSCU && tid == 0) {
                    spin_until(&g_ccnt[cb + sc + 2], 8);
                    __threadfence();
                }
                __syncthreads();
                if (sc + 2 < NSCU) LDG_CHUNK(sc + 2);
            }
#undef LDG_CHUNK
#undef STS_CHUNK

            int slot = s * 2 + half;
            float* p0 = &g_pnum[((size_t)slot * NT + r0) * NCLS];
            float* p1 = &g_pnum[((size_t)slot * NT + r1) * NCLS];
            *reinterpret_cast<float2*>(p0 + 2 * tg)     = make_float2(d10, d11);
            *reinterpret_cast<float2*>(p0 + 8 + 2 * tg) = make_float2(d20, d21);
            *reinterpret_cast<float2*>(p1 + 2 * tg)     = make_float2(d12, d13);
            *reinterpret_cast<float2*>(p1 + 8 + 2 * tg) = make_float2(d22, d23);
            if (tg == 0) {
                g_pden[(size_t)slot * NT + r0] = e0;
                g_pden[(size_t)slot * NT + r1] = e2;
            }
        }
    }
}

// ---------------- reduce: sum 16 slots, normalize, reset queue state ----------------
__global__ __launch_bounds__(256) void reduce_kernel(float* __restrict__ out) {
    int idx = blockIdx.x * 256 + threadIdx.x;     // 0 .. NT*4-1
    int i   = idx >> 2;
    int tg  = idx & 3;

    float4 n = make_float4(0, 0, 0, 0);
    float d = 0.f;
    #pragma unroll
    for (int sl = 0; sl < NSLOT; sl++) {
        float4 a = *reinterpret_cast<const float4*>(
            &g_pnum[((size_t)sl * NT + i) * NCLS + tg * 4]);
        n.x += a.x; n.y += a.y; n.z += a.z; n.w += a.w;
        d += g_pden[(size_t)sl * NT + i];
    }
    float inv = 1.0f / d;
    n.x *= inv; n.y *= inv; n.z *= inv; n.w *= inv;
    *reinterpret_cast<float4*>(out + (size_t)i * NCLS + tg * 4) = n;

    // reset ticket/flag state for next graph replay (stream-ordered before next launch)
    if (blockIdx.x == 0) {
        if (threadIdx.x == 0) { g_ticket = 0; g_qcnt = 0; }
        if (threadIdx.x < 64) g_ccnt[threadIdx.x] = 0;
    }
}

// ---------------- launch ----------------
extern "C" void kernel_launch(void* const* d_in, const int* in_sizes, int n_in,
                              void* d_out, int out_size) {
    const float* xtr = (const float*)d_in[0];   // [16384, 512]
    const float* ytr = (const float*)d_in[1];   // [16384, 16]
    const float* xt  = (const float*)d_in[2];   // [8192, 512]
    const float* A   = (const float*)d_in[3];   // [512, 2]
    float* out = (float*)d_out;                 // [8192, 16]

    fused_kernel<<<GRID_FUSED, 128>>>(xtr, ytr, xt, A);
    reduce_kernel<<<NT * 4 / 256, 256>>>(out);
}